// round 3
// baseline (speedup 1.0000x reference)
#include <cuda_runtime.h>
#include <cstdint>
#include <cstddef>

#define BS 256
#define KDIM 1024
#define NDIM 1024
#define NSTATES 20
#define TN 64       // n-columns per block (2 per lane)
#define RCH 16      // max rows (samples) per block chunk
#define KC 512      // k elements staged per chunk
#define NWARPS 8
#define KSL (KC / NWARPS)   // 64 k per warp per chunk
#define NTHREADS 256

__device__ __forceinline__ unsigned long long mul2(unsigned long long a, unsigned long long b) {
    unsigned long long d;
    asm("mul.rn.f32x2 %0, %1, %2;" : "=l"(d) : "l"(a), "l"(b));
    return d;
}
__device__ __forceinline__ unsigned long long fma2(unsigned long long a, unsigned long long b, unsigned long long c) {
    unsigned long long d;
    asm("fma.rn.f32x2 %0, %1, %2, %3;" : "=l"(d) : "l"(a), "l"(b), "l"(c));
    return d;
}

// Block = (n-tile, state, row-chunk). Computes out[rows_of_state, n0:n0+64].
__global__ __launch_bounds__(NTHREADS, 2)
void masked_dense_kernel(const float* __restrict__ x,
                         const int* __restrict__ state,
                         const float* __restrict__ kern,
                         const float* __restrict__ masks,
                         float* __restrict__ out)
{
    // 64KB dynamic smem: x chunk duplicated into f32x2 pairs [RCH][KC];
    // reused after the mainloop as the 8-warp reduction buffer [8][RCH*TN] floats.
    extern __shared__ unsigned long long xs2[];
    __shared__ int rowlist[RCH];
    __shared__ int warp_cnt[NWARPS];

    const int t = threadIdx.x;
    const int w = t >> 5;
    const int lane = t & 31;
    const int s = blockIdx.y;
    const int z = blockIdx.z;
    const int n0 = blockIdx.x * TN;

    // ---- build row list for this (state, chunk) via ballots ----
    const int my_state = state[t];               // NTHREADS == BS
    const bool match = (my_state == s);
    const unsigned bal = __ballot_sync(0xffffffffu, match);
    if (lane == 0) warp_cnt[w] = __popc(bal);
    __syncthreads();

    int total = 0, before = 0;
#pragma unroll
    for (int i = 0; i < NWARPS; i++) {
        const int c = warp_cnt[i];
        if (i < w) before += c;
        total += c;
    }
    const int zbase = z * RCH;
    if (total <= zbase) return;                  // empty chunk: whole block exits
    const int nrows = min(total - zbase, RCH);

    const int rank = before + __popc(bal & ((1u << lane) - 1u));
    if (match && rank >= zbase && rank < zbase + RCH)
        rowlist[rank - zbase] = t;
    __syncthreads();

    // ---- accumulators: 16 rows x 2 cols (one f32x2 pair per row) ----
    unsigned long long acc[RCH];
#pragma unroll
    for (int r = 0; r < RCH; r++) acc[r] = 0ull;

    const int gc = n0 + 2 * lane;                // this lane's 2 global columns

    for (int kc = 0; kc < KDIM / KC; kc++) {
        if (kc > 0) __syncthreads();             // previous chunk fully consumed
        // stage x[rows][kc*KC : +KC], duplicated (v,v) for packed FMA
        {
            float4* xsf4 = (float4*)xs2;         // two duplicated pairs per float4
            for (int e4 = t; e4 < RCH * (KC / 4); e4 += NTHREADS) {
                const int r = e4 >> 7;                       // KC/4 == 128
                const int k4 = (e4 & 127) * 4;
                float4 v;
                if (r < nrows)
                    v = *(const float4*)&x[(size_t)rowlist[r] * KDIM + kc * KC + k4];
                else
                    v = make_float4(0.f, 0.f, 0.f, 0.f);
                const int base = (r * KC + k4) >> 1;         // float4 index
                xsf4[base + 0] = make_float4(v.x, v.x, v.y, v.y);
                xsf4[base + 1] = make_float4(v.z, v.z, v.w, v.w);
            }
        }
        __syncthreads();

        // warp w handles k in [kbase, kbase+KSL); lane handles 2 cols
        const int kbase = kc * KC + w * KSL;
        const float* mp = masks + ((size_t)s * KDIM + kbase) * NDIM + gc;
        const float* kp = kern + (size_t)kbase * NDIM + gc;
        // x broadcast source: ulonglong2 = two consecutive duplicated k pairs
        const ulonglong2* xrow2 = (const ulonglong2*)(xs2 + w * KSL);

        // groups of 4 k-rows, prefetch distance 2: 16 LDG.64 in flight
        constexpr int NG = KSL / 4;              // 16 groups
        unsigned long long mbuf[2][4], kbuf[2][4];
#pragma unroll
        for (int sl = 0; sl < 2; sl++)
#pragma unroll
            for (int j = 0; j < 4; j++) {
                const size_t off = (size_t)(sl * 4 + j) * NDIM;
                mbuf[sl][j] = *(const unsigned long long*)(mp + off);
                kbuf[sl][j] = *(const unsigned long long*)(kp + off);
            }

#pragma unroll
        for (int g = 0; g < NG; g++) {
            const int cur = g & 1;
            // consume buffers into masked weights
            unsigned long long wv[4];
#pragma unroll
            for (int j = 0; j < 4; j++) wv[j] = mul2(mbuf[cur][j], kbuf[cur][j]);
            // refill this slot with group g+2 (buffers now dead)
            if (g + 2 < NG) {
#pragma unroll
                for (int j = 0; j < 4; j++) {
                    const size_t off = (size_t)((g + 2) * 4 + j) * NDIM;
                    mbuf[cur][j] = *(const unsigned long long*)(mp + off);
                    kbuf[cur][j] = *(const unsigned long long*)(kp + off);
                }
            }
            // compute: two k-pairs, one broadcast LDS.128 per row per pair
#pragma unroll
            for (int p = 0; p < 2; p++) {
                const int pi = g * 2 + p;        // ulonglong2 index within row
#pragma unroll
                for (int r = 0; r < RCH; r++) {
                    const ulonglong2 xv = xrow2[r * (KC / 2) + pi];
                    acc[r] = fma2(xv.x, wv[2 * p], acc[r]);
                    acc[r] = fma2(xv.y, wv[2 * p + 1], acc[r]);
                }
            }
        }
    }
    __syncthreads();   // all warps done reading xs2 before overlay

    // ---- cross-warp k-reduction via flat smem buffer [8][RCH*TN] floats ----
    {
        unsigned long long* myb = xs2 + (size_t)w * (RCH * TN / 2);
#pragma unroll
        for (int r = 0; r < RCH; r++)
            myb[r * (TN / 2) + lane] = acc[r];
    }
    __syncthreads();

    const float* redf = (const float*)xs2;
    for (int e = t; e < nrows * TN; e += NTHREADS) {
        float v = 0.f;
#pragma unroll
        for (int ww = 0; ww < NWARPS; ww++) v += redf[ww * (RCH * TN) + e];
        v = fmaxf(v, 0.f);                         // ReLU
        const int r = e >> 6;                      // TN == 64
        const int c = e & 63;
        out[(size_t)rowlist[r] * NDIM + n0 + c] = v;
    }
}

extern "C" void kernel_launch(void* const* d_in, const int* in_sizes, int n_in,
                              void* d_out, int out_size)
{
    // Identify inputs by element count (all distinct): x=262144, state=256,
    // kernel=1048576, masks=20971520.
    const float* x = nullptr;
    const int* state = nullptr;
    const float* kern = nullptr;
    const float* masks = nullptr;
    for (int i = 0; i < n_in; i++) {
        switch (in_sizes[i]) {
            case BS * KDIM:          x = (const float*)d_in[i]; break;
            case BS:                 state = (const int*)d_in[i]; break;
            case KDIM * NDIM:        kern = (const float*)d_in[i]; break;
            case NSTATES * KDIM * NDIM: masks = (const float*)d_in[i]; break;
            default: break;
        }
    }
    float* out = (float*)d_out;

    const int smem_bytes = RCH * KC * (int)sizeof(unsigned long long);  // 64 KB
    static bool attr_set = false;
    if (!attr_set) {
        cudaFuncSetAttribute(masked_dense_kernel,
                             cudaFuncAttributeMaxDynamicSharedMemorySize, smem_bytes);
        attr_set = true;
    }

    dim3 grid(NDIM / TN, NSTATES, BS / RCH);   // (16, 20, 16)
    masked_dense_kernel<<<grid, NTHREADS, smem_bytes>>>(x, state, kern, masks, out);
}